// round 12
// baseline (speedup 1.0000x reference)
#include <cuda_runtime.h>
#include <cuda_bf16.h>

// Problem shape (fixed by dataset)
#define NMAX 50000
#define EMAX 600000
#define DIM  128
#define GR   16        // rows per block in QKV GEMM (8+8 across thread halves)
#define SCAN_TILE 2048 // elems per scan block (256 thr x 8)
#define SCAN_MAXB 64   // max scan blocks (50000/2048 -> 25)

// ---------------- device scratch (static allocation only) ----------------
__device__ float g_Q[NMAX * DIM];
__device__ float g_K[NMAX * DIM];
__device__ float g_V[NMAX * DIM];
__device__ float g_WT[3][DIM * DIM];   // transposed weights: g_WT[m][j*DIM+k] = w_m[k*DIM+j]
__device__ int   g_deg[NMAX + 8];      // zero-init at load; re-zeroed by scan_p3 each call
__device__ int   g_rowptr[NMAX + 1];
__device__ int   g_cursor[NMAX];
__device__ int   g_ecol[EMAX];         // cols permuted into CSR order
__device__ int   g_bsum[SCAN_MAXB];
__device__ int   g_boff[SCAN_MAXB];

// ---------------- packed f32x2 helpers ----------------
__device__ __forceinline__ void ffma2(unsigned long long& acc,
                                      unsigned long long a,
                                      unsigned long long b) {
    asm("fma.rn.f32x2 %0, %1, %2, %0;" : "+l"(acc) : "l"(a), "l"(b));
}
__device__ __forceinline__ float hsum2(unsigned long long v) {
    unsigned a, b;
    asm("mov.b64 {%0, %1}, %2;" : "=r"(a), "=r"(b) : "l"(v));
    return __uint_as_float(a) + __uint_as_float(b);   // even-k part + odd-k part
}

// ---------------- kernel A: tiled weight transpose (once per launch) ----------------
// g_WT[m][j][k] = w_m[k][j].  grid (4,4,3), block (32,8).
__global__ void wtrans_kernel(const float* __restrict__ wq,
                              const float* __restrict__ wk,
                              const float* __restrict__ wv) {
    __shared__ float t[32][33];
    const float* src = (blockIdx.z == 0) ? wq : (blockIdx.z == 1) ? wk : wv;
    float* dst = g_WT[blockIdx.z];
    int k0 = blockIdx.x * 32;   // source row block   (k)
    int j0 = blockIdx.y * 32;   // source column block (j)
    #pragma unroll
    for (int r = 0; r < 32; r += 8) {
        int k = k0 + threadIdx.y + r;
        t[threadIdx.y + r][threadIdx.x] = src[k * DIM + j0 + threadIdx.x];
    }
    __syncthreads();
    #pragma unroll
    for (int r = 0; r < 32; r += 8) {
        int j = j0 + threadIdx.y + r;
        dst[j * DIM + k0 + threadIdx.x] = t[threadIdx.x][threadIdx.y + r];
    }
}

// ---------------- kernel 1: fused Q/K/V projection (k-packed f32x2) ----------------
// 256 threads: j = tid&127 (output column), half = tid>>7 owns 8 of 16 rows.
// Lanes of each f32x2 accumulator hold even-k / odd-k partial sums; one
// horizontal add at the end. Both FFMA2 operands are contiguous pairs:
//   e2 from row-major smem tile (LDS.128 = 4 k's, warp-broadcast)
//   w2 from transposed weights  (LDG.128 = 4 k's, coalesced-ish per warp)
// -> zero broadcast movs, 4x fewer weight LDGs than R11.
__global__ void __launch_bounds__(256) qkv_kernel(
    const float* __restrict__ emb, int n)
{
    __shared__ __align__(16) float et[GR][DIM + 4];   // 132 floats = 528B stride (16B aligned)
    const int j    = threadIdx.x & 127;               // output column 0..127
    const int half = threadIdx.x >> 7;                // 0 or 1
    const int rb   = half * 8;                        // first row of this half's 8 rows
    const int r0   = blockIdx.x * GR;

    // load tile row-major: thread j writes column j of its half's rows (coalesced)
    #pragma unroll
    for (int r = 0; r < 8; r++) {
        int row = r0 + rb + r;
        et[rb + r][j] = (row < n) ? emb[row * DIM + j] : 0.f;
    }
    __syncthreads();

    const float* wqT = &g_WT[0][j * DIM];
    const float* wkT = &g_WT[1][j * DIM];
    const float* wvT = &g_WT[2][j * DIM];

    unsigned long long acc[3][8];   // [matrix][row], 48 regs
    #pragma unroll
    for (int m = 0; m < 3; m++)
        #pragma unroll
        for (int r = 0; r < 8; r++) acc[m][r] = 0ull;

    #pragma unroll 2
    for (int kk = 0; kk < DIM; kk += 4) {
        ulonglong2 wq2 = *(const ulonglong2*)&wqT[kk];   // k..k+3 of column j
        ulonglong2 wk2 = *(const ulonglong2*)&wkT[kk];
        ulonglong2 wv2 = *(const ulonglong2*)&wvT[kk];
        #pragma unroll
        for (int r = 0; r < 8; r++) {
            ulonglong2 e2 = *(const ulonglong2*)&et[rb + r][kk];  // broadcast LDS.128
            ffma2(acc[0][r], e2.x, wq2.x);
            ffma2(acc[0][r], e2.y, wq2.y);
            ffma2(acc[1][r], e2.x, wk2.x);
            ffma2(acc[1][r], e2.y, wk2.y);
            ffma2(acc[2][r], e2.x, wv2.x);
            ffma2(acc[2][r], e2.y, wv2.y);
        }
    }

    #pragma unroll
    for (int r = 0; r < 8; r++) {
        int row = r0 + rb + r;
        if (row < n) {
            g_Q[row * DIM + j] = hsum2(acc[0][r]);
            g_K[row * DIM + j] = hsum2(acc[1][r]);
            g_V[row * DIM + j] = hsum2(acc[2][r]);
        }
    }
}

// ---------------- kernel 2: degree histogram ----------------
__global__ void hist_kernel(const int* __restrict__ rows, int E) {
    int i = blockIdx.x * blockDim.x + threadIdx.x;
    if (i < E) atomicAdd(&g_deg[rows[i]], 1);
}

// ---------------- scan phase 1: per-block sums ----------------
__global__ void __launch_bounds__(256) scan_p1_kernel(int n) {
    __shared__ int ws[8];
    const int tid  = threadIdx.x;
    const int lane = tid & 31;
    const int wid  = tid >> 5;
    int base = blockIdx.x * SCAN_TILE + tid * 8;

    const int4* d4 = (const int4*)&g_deg[base];
    int s = 0;
    if (base < n) {
        int4 a = d4[0], b = d4[1];
        s = a.x + a.y + a.z + a.w + b.x + b.y + b.z + b.w;  // pad is zero
    }
    #pragma unroll
    for (int off = 16; off; off >>= 1) s += __shfl_xor_sync(0xffffffffu, s, off);
    if (lane == 0) ws[wid] = s;
    __syncthreads();
    if (tid == 0) {
        int t = 0;
        #pragma unroll
        for (int w = 0; w < 8; w++) t += ws[w];
        g_bsum[blockIdx.x] = t;
    }
}

// ---------------- scan phase 2: scan block sums (1 warp) ----------------
__global__ void scan_p2_kernel(int nblocks, int n) {
    int lane = threadIdx.x;
    __shared__ int carry;
    if (lane == 0) carry = 0;
    __syncwarp();
    for (int b0 = 0; b0 < nblocks; b0 += 32) {
        int i = b0 + lane;
        int v = (i < nblocks) ? g_bsum[i] : 0;
        int inc = v;
        #pragma unroll
        for (int off = 1; off < 32; off <<= 1) {
            int t = __shfl_up_sync(0xffffffffu, inc, off);
            if (lane >= off) inc += t;
        }
        int c = carry;
        if (i < nblocks) g_boff[i] = c + inc - v;
        if (lane == 31) carry = c + inc;
        __syncwarp();
    }
    if (lane == 0) g_rowptr[n] = carry;   // grand total
}

// ---------------- scan phase 3: rescan tiles, then re-zero deg for next call ----------------
__global__ void __launch_bounds__(256) scan_p3_kernel(int n) {
    __shared__ int warp_off[8];
    const int tid  = threadIdx.x;
    const int lane = tid & 31;
    const int wid  = tid >> 5;
    int base = blockIdx.x * SCAN_TILE + tid * 8;

    int v[8];
    int tot = 0;
    if (base < n) {
        int4* d4 = (int4*)&g_deg[base];
        int4 a = d4[0], b = d4[1];
        int d[8] = {a.x, a.y, a.z, a.w, b.x, b.y, b.z, b.w};
        #pragma unroll
        for (int i = 0; i < 8; i++) { v[i] = tot; tot += d[i]; }
        // leave deg zeroed so next graph replay's hist starts clean
        d4[0] = make_int4(0, 0, 0, 0);
        d4[1] = make_int4(0, 0, 0, 0);
    } else {
        #pragma unroll
        for (int i = 0; i < 8; i++) v[i] = 0;
    }

    int inc = tot;
    #pragma unroll
    for (int off = 1; off < 32; off <<= 1) {
        int t = __shfl_up_sync(0xffffffffu, inc, off);
        if (lane >= off) inc += t;
    }
    if (lane == 31) warp_off[wid] = inc;
    int texcl = inc - tot;
    __syncthreads();

    if (wid == 0 && lane < 8) {
        int w = warp_off[lane];
        int wi = w;
        #pragma unroll
        for (int off = 1; off < 8; off <<= 1) {
            int t = __shfl_up_sync(0x000000ffu, wi, off);
            if (lane >= off) wi += t;
        }
        warp_off[lane] = wi - w;
    }
    __syncthreads();

    int b = g_boff[blockIdx.x] + warp_off[wid] + texcl;
    #pragma unroll
    for (int i = 0; i < 8; i++) {
        int idx = base + i;
        if (idx < n) {
            int val = b + v[i];
            g_rowptr[idx] = val;
            g_cursor[idx] = val;
        }
    }
}

// ---------------- kernel 4: scatter col ids into CSR order ----------------
__global__ void scatter_kernel(const int* __restrict__ rows,
                               const int* __restrict__ cols, int E) {
    int i = blockIdx.x * blockDim.x + threadIdx.x;
    if (i < E) {
        int pos = atomicAdd(&g_cursor[rows[i]], 1);
        g_ecol[pos] = cols[i];
    }
}

// ---------------- kernel 5: fused single-pass segment-softmax attention ----------------
// One warp per destination node. Lane l holds dims [4l, 4l+4); head = l>>3.
// out = (sum_e ea_e * v_e) / (sum_e ea_e + 1e-8)  — norm factored out of the sum.
__global__ void __launch_bounds__(256) attn_kernel(float* __restrict__ out, int n)
{
    int gw   = (blockIdx.x * blockDim.x + threadIdx.x) >> 5;
    int lane = threadIdx.x & 31;
    if (gw >= n) return;

    const float4* Q4 = (const float4*)g_Q;
    const float4* K4 = (const float4*)g_K;
    const float4* V4 = (const float4*)g_V;

    float4 qv = Q4[gw * 32 + lane];
    int beg = g_rowptr[gw];
    int end = g_rowptr[gw + 1];

    float nsum = 0.f;
    float4 acc = make_float4(0.f, 0.f, 0.f, 0.f);
    for (int idx = beg; idx < end; idx++) {
        int c = g_ecol[idx];                      // sequential read, CSR order
        float4 kv = K4[c * 32 + lane];            // two independent row gathers
        float4 vv = V4[c * 32 + lane];
        float p = fmaf(qv.x, kv.x, fmaf(qv.y, kv.y, fmaf(qv.z, kv.z, qv.w * kv.w)));
        p += __shfl_xor_sync(0xffffffffu, p, 1);
        p += __shfl_xor_sync(0xffffffffu, p, 2);
        p += __shfl_xor_sync(0xffffffffu, p, 4);  // full head dot in all 8 lanes of group
        float a  = fminf(fmaxf(p, -10.f), 10.f);
        float ea = __expf(a);
        nsum += ea;
        acc.x = fmaf(ea, vv.x, acc.x);
        acc.y = fmaf(ea, vv.y, acc.y);
        acc.z = fmaf(ea, vv.z, acc.z);
        acc.w = fmaf(ea, vv.w, acc.w);
    }
    float inv = 1.f / (nsum + 1e-8f);
    acc.x *= inv; acc.y *= inv; acc.z *= inv; acc.w *= inv;
    ((float4*)out)[gw * 32 + lane] = acc;
}

// ---------------- launch ----------------
// Order chosen so the profiled launch (index 3) is qkv_kernel.
extern "C" void kernel_launch(void* const* d_in, const int* in_sizes, int n_in,
                              void* d_out, int out_size) {
    const float* emb  = (const float*)d_in[0];
    const float* qW   = (const float*)d_in[1];
    const float* kW   = (const float*)d_in[2];
    const float* vW   = (const float*)d_in[3];
    const int*   rows = (const int*)d_in[4];
    const int*   cols = (const int*)d_in[5];
    float*       out  = (float*)d_out;

    const int N = in_sizes[0] / DIM;   // 50000
    const int E = in_sizes[4];         // 600000
    const int nsb = (N + SCAN_TILE - 1) / SCAN_TILE;   // 25

    hist_kernel<<<(E + 255) / 256, 256>>>(rows, E);              // 0
    { dim3 g(4, 4, 3), b(32, 8); wtrans_kernel<<<g, b>>>(qW, kW, vW); } // 1
    scan_p1_kernel<<<nsb, 256>>>(N);                             // 2
    qkv_kernel<<<(N + GR - 1) / GR, 256>>>(emb, N);              // 3  <- profiled
    scan_p2_kernel<<<1, 32>>>(nsb, N);                           // 4
    scan_p3_kernel<<<nsb, 256>>>(N);                             // 5
    scatter_kernel<<<(E + 255) / 256, 256>>>(rows, cols, E);     // 6
    attn_kernel<<<(N + 7) / 8, 256>>>(out, N);                   // 7
}

// round 13
// speedup vs baseline: 1.9133x; 1.9133x over previous
#include <cuda_runtime.h>
#include <cuda_bf16.h>

// Problem shape (fixed by dataset)
#define NMAX 50000
#define EMAX 600000
#define DIM  128
#define GR   32        // rows per block in QKV GEMM (16+16 across thread halves)
#define SCAN_TILE 2048 // elems per scan block (256 thr x 8)
#define SCAN_MAXB 64   // max scan blocks (50000/2048 -> 25)

// ---------------- device scratch (static allocation only) ----------------
__device__ float g_Q[NMAX * DIM];
__device__ float g_K[NMAX * DIM];
__device__ float g_V[NMAX * DIM];
__device__ int   g_deg[NMAX + 8];      // zero-init at load; re-zeroed by scan_p3 each call
__device__ int   g_rowptr[NMAX + 1];
__device__ int   g_cursor[NMAX];
__device__ int   g_ecol[EMAX];         // cols permuted into CSR order
__device__ int   g_bsum[SCAN_MAXB];
__device__ int   g_boff[SCAN_MAXB];

// ---------------- packed f32x2 helpers ----------------
__device__ __forceinline__ void ffma2(unsigned long long& acc,
                                      unsigned long long a,
                                      unsigned long long b) {
    asm("fma.rn.f32x2 %0, %1, %2, %0;" : "+l"(acc) : "l"(a), "l"(b));
}
__device__ __forceinline__ unsigned long long bcast2(float x) {
    unsigned long long r;
    unsigned u = __float_as_uint(x);
    asm("mov.b64 %0, {%1, %1};" : "=l"(r) : "r"(u));
    return r;
}
__device__ __forceinline__ void unpack2(unsigned long long v, float& lo, float& hi) {
    unsigned a, b;
    asm("mov.b64 {%0, %1}, %2;" : "=r"(a), "=r"(b) : "l"(v));
    lo = __uint_as_float(a);
    hi = __uint_as_float(b);
}

// ---------------- kernel 1: fused Q/K/V projection (row-packed f32x2) ----------------
// 256 threads: j = tid&127 (output column), half = tid>>7 owns 16 of the 32 rows.
// Coalesced scalar weight LDGs (R11-proven); 8 packed accumulators per matrix
// (48 regs) so 3 blocks/SM; 24 FFMA2 per (k, 3-LDG+3-bcast) -> ~71% issue eff.
__global__ void __launch_bounds__(256, 3) qkv_kernel(
    const float* __restrict__ emb,
    const float* __restrict__ wq,
    const float* __restrict__ wk,
    const float* __restrict__ wv,
    int n)
{
    __shared__ __align__(16) float et[DIM][36];   // k-major; 144B row stride (16B aligned)
    const int j    = threadIdx.x & 127;           // output column 0..127
    const int half = threadIdx.x >> 7;            // 0 or 1
    const int rb   = half * 16;                   // first row of this half within tile
    const int r0   = blockIdx.x * GR;

    // thread loads its half's 16 rows for k=j (k-major tile, coalesced per row)
    #pragma unroll
    for (int r = 0; r < 16; r++) {
        int row = r0 + rb + r;
        et[j][rb + r] = (row < n) ? emb[row * DIM + j] : 0.f;
    }
    __syncthreads();

    // 8 packed accumulators per matrix: pair i = rows (rb+2i, rb+2i+1)
    unsigned long long aq[8], ak[8], av[8];
    #pragma unroll
    for (int i = 0; i < 8; i++) { aq[i] = 0ull; ak[i] = 0ull; av[i] = 0ull; }

    #pragma unroll 2
    for (int k = 0; k < DIM; k++) {
        unsigned long long q2 = bcast2(__ldg(&wq[k * DIM + j]));
        unsigned long long k2 = bcast2(__ldg(&wk[k * DIM + j]));
        unsigned long long v2 = bcast2(__ldg(&wv[k * DIM + j]));
        const ulonglong2* ep = (const ulonglong2*)(&et[k][rb]);  // 16B aligned (144k+64h)
        #pragma unroll
        for (int p = 0; p < 4; p++) {
            ulonglong2 e2 = ep[p];    // 4 rows packed pairwise; warp-broadcast read
            ffma2(aq[2 * p],     e2.x, q2);
            ffma2(aq[2 * p + 1], e2.y, q2);
            ffma2(ak[2 * p],     e2.x, k2);
            ffma2(ak[2 * p + 1], e2.y, k2);
            ffma2(av[2 * p],     e2.x, v2);
            ffma2(av[2 * p + 1], e2.y, v2);
        }
    }

    #pragma unroll
    for (int i = 0; i < 8; i++) {
        float qlo, qhi, klo, khi, vlo, vhi;
        unpack2(aq[i], qlo, qhi);
        unpack2(ak[i], klo, khi);
        unpack2(av[i], vlo, vhi);
        int row = r0 + rb + 2 * i;
        if (row < n) {
            g_Q[row * DIM + j] = qlo;
            g_K[row * DIM + j] = klo;
            g_V[row * DIM + j] = vlo;
        }
        if (row + 1 < n) {
            g_Q[(row + 1) * DIM + j] = qhi;
            g_K[(row + 1) * DIM + j] = khi;
            g_V[(row + 1) * DIM + j] = vhi;
        }
    }
}

// ---------------- kernel 2: degree histogram ----------------
__global__ void hist_kernel(const int* __restrict__ rows, int E) {
    int i = blockIdx.x * blockDim.x + threadIdx.x;
    if (i < E) atomicAdd(&g_deg[rows[i]], 1);
}

// ---------------- scan phase 1: per-block sums ----------------
__global__ void __launch_bounds__(256) scan_p1_kernel(int n) {
    __shared__ int ws[8];
    const int tid  = threadIdx.x;
    const int lane = tid & 31;
    const int wid  = tid >> 5;
    int base = blockIdx.x * SCAN_TILE + tid * 8;

    const int4* d4 = (const int4*)&g_deg[base];
    int s = 0;
    if (base < n) {
        int4 a = d4[0], b = d4[1];
        s = a.x + a.y + a.z + a.w + b.x + b.y + b.z + b.w;  // pad is zero
    }
    #pragma unroll
    for (int off = 16; off; off >>= 1) s += __shfl_xor_sync(0xffffffffu, s, off);
    if (lane == 0) ws[wid] = s;
    __syncthreads();
    if (tid == 0) {
        int t = 0;
        #pragma unroll
        for (int w = 0; w < 8; w++) t += ws[w];
        g_bsum[blockIdx.x] = t;
    }
}

// ---------------- scan phase 2: scan block sums (1 warp) ----------------
__global__ void scan_p2_kernel(int nblocks, int n) {
    int lane = threadIdx.x;
    __shared__ int carry;
    if (lane == 0) carry = 0;
    __syncwarp();
    for (int b0 = 0; b0 < nblocks; b0 += 32) {
        int i = b0 + lane;
        int v = (i < nblocks) ? g_bsum[i] : 0;
        int inc = v;
        #pragma unroll
        for (int off = 1; off < 32; off <<= 1) {
            int t = __shfl_up_sync(0xffffffffu, inc, off);
            if (lane >= off) inc += t;
        }
        int c = carry;
        if (i < nblocks) g_boff[i] = c + inc - v;
        if (lane == 31) carry = c + inc;
        __syncwarp();
    }
    if (lane == 0) g_rowptr[n] = carry;   // grand total
}

// ---------------- scan phase 3: rescan tiles, then re-zero deg for next call ----------------
__global__ void __launch_bounds__(256) scan_p3_kernel(int n) {
    __shared__ int warp_off[8];
    const int tid  = threadIdx.x;
    const int lane = tid & 31;
    const int wid  = tid >> 5;
    int base = blockIdx.x * SCAN_TILE + tid * 8;

    int v[8];
    int tot = 0;
    if (base < n) {
        int4* d4 = (int4*)&g_deg[base];
        int4 a = d4[0], b = d4[1];
        int d[8] = {a.x, a.y, a.z, a.w, b.x, b.y, b.z, b.w};
        #pragma unroll
        for (int i = 0; i < 8; i++) { v[i] = tot; tot += d[i]; }
        // leave deg zeroed so next graph replay's hist starts clean
        d4[0] = make_int4(0, 0, 0, 0);
        d4[1] = make_int4(0, 0, 0, 0);
    } else {
        #pragma unroll
        for (int i = 0; i < 8; i++) v[i] = 0;
    }

    int inc = tot;
    #pragma unroll
    for (int off = 1; off < 32; off <<= 1) {
        int t = __shfl_up_sync(0xffffffffu, inc, off);
        if (lane >= off) inc += t;
    }
    if (lane == 31) warp_off[wid] = inc;
    int texcl = inc - tot;
    __syncthreads();

    if (wid == 0 && lane < 8) {
        int w = warp_off[lane];
        int wi = w;
        #pragma unroll
        for (int off = 1; off < 8; off <<= 1) {
            int t = __shfl_up_sync(0x000000ffu, wi, off);
            if (lane >= off) wi += t;
        }
        warp_off[lane] = wi - w;
    }
    __syncthreads();

    int b = g_boff[blockIdx.x] + warp_off[wid] + texcl;
    #pragma unroll
    for (int i = 0; i < 8; i++) {
        int idx = base + i;
        if (idx < n) {
            int val = b + v[i];
            g_rowptr[idx] = val;
            g_cursor[idx] = val;
        }
    }
}

// ---------------- kernel 4: scatter col ids into CSR order ----------------
__global__ void scatter_kernel(const int* __restrict__ rows,
                               const int* __restrict__ cols, int E) {
    int i = blockIdx.x * blockDim.x + threadIdx.x;
    if (i < E) {
        int pos = atomicAdd(&g_cursor[rows[i]], 1);
        g_ecol[pos] = cols[i];
    }
}

// ---------------- kernel 5: fused single-pass segment-softmax attention ----------------
// One warp per destination node. Lane l holds dims [4l, 4l+4); head = l>>3.
// out = (sum_e ea_e * v_e) / (sum_e ea_e + 1e-8)  — norm factored out of the sum.
__global__ void __launch_bounds__(256) attn_kernel(float* __restrict__ out, int n)
{
    int gw   = (blockIdx.x * blockDim.x + threadIdx.x) >> 5;
    int lane = threadIdx.x & 31;
    if (gw >= n) return;

    const float4* Q4 = (const float4*)g_Q;
    const float4* K4 = (const float4*)g_K;
    const float4* V4 = (const float4*)g_V;

    float4 qv = Q4[gw * 32 + lane];
    int beg = g_rowptr[gw];
    int end = g_rowptr[gw + 1];

    float nsum = 0.f;
    float4 acc = make_float4(0.f, 0.f, 0.f, 0.f);
    for (int idx = beg; idx < end; idx++) {
        int c = g_ecol[idx];                      // sequential read, CSR order
        float4 kv = K4[c * 32 + lane];            // two independent row gathers
        float4 vv = V4[c * 32 + lane];
        float p = fmaf(qv.x, kv.x, fmaf(qv.y, kv.y, fmaf(qv.z, kv.z, qv.w * kv.w)));
        p += __shfl_xor_sync(0xffffffffu, p, 1);
        p += __shfl_xor_sync(0xffffffffu, p, 2);
        p += __shfl_xor_sync(0xffffffffu, p, 4);  // full head dot in all 8 lanes of group
        float a  = fminf(fmaxf(p, -10.f), 10.f);
        float ea = __expf(a);
        nsum += ea;
        acc.x = fmaf(ea, vv.x, acc.x);
        acc.y = fmaf(ea, vv.y, acc.y);
        acc.z = fmaf(ea, vv.z, acc.z);
        acc.w = fmaf(ea, vv.w, acc.w);
    }
    float inv = 1.f / (nsum + 1e-8f);
    acc.x *= inv; acc.y *= inv; acc.z *= inv; acc.w *= inv;
    ((float4*)out)[gw * 32 + lane] = acc;
}

// ---------------- launch ----------------
// Order chosen so the profiled launch (index 3) is qkv_kernel.
extern "C" void kernel_launch(void* const* d_in, const int* in_sizes, int n_in,
                              void* d_out, int out_size) {
    const float* emb  = (const float*)d_in[0];
    const float* qW   = (const float*)d_in[1];
    const float* kW   = (const float*)d_in[2];
    const float* vW   = (const float*)d_in[3];
    const int*   rows = (const int*)d_in[4];
    const int*   cols = (const int*)d_in[5];
    float*       out  = (float*)d_out;

    const int N = in_sizes[0] / DIM;   // 50000
    const int E = in_sizes[4];         // 600000
    const int nsb = (N + SCAN_TILE - 1) / SCAN_TILE;   // 25

    hist_kernel<<<(E + 255) / 256, 256>>>(rows, E);              // 0
    scan_p1_kernel<<<nsb, 256>>>(N);                             // 1
    scan_p2_kernel<<<1, 32>>>(nsb, N);                           // 2
    qkv_kernel<<<(N + GR - 1) / GR, 256>>>(emb, qW, kW, vW, N);  // 3  <- profiled
    scan_p3_kernel<<<nsb, 256>>>(N);                             // 4
    scatter_kernel<<<(E + 255) / 256, 256>>>(rows, cols, E);     // 5
    attn_kernel<<<(N + 7) / 8, 256>>>(out, N);                   // 6
}